// round 3
// baseline (speedup 1.0000x reference)
#include <cuda_runtime.h>
#include <math.h>

// Problem constants
#define B_  64
#define T_  512
#define H_  50
#define G_  200     // 4*H
#define F_  513
#define M_  (B_*T_) // 32768

// Scratch (device globals: allocation-free per harness rules)
__device__ float g_xg[(size_t)M_ * G_];   // 26.2 MB
__device__ float g_hs[(size_t)M_ * H_];   // 6.6 MB

// ---------------- f32x2 packed-FMA helpers (sm_100+ PTX) ----------------
__device__ __forceinline__ unsigned long long pk2(float lo, float hi) {
    unsigned long long r;
    asm("mov.b64 %0, {%1, %2};" : "=l"(r) : "f"(lo), "f"(hi));
    return r;
}
__device__ __forceinline__ void upk2(unsigned long long v, float& lo, float& hi) {
    asm("mov.b64 {%0, %1}, %2;" : "=f"(lo), "=f"(hi) : "l"(v));
}
__device__ __forceinline__ void fma2(unsigned long long& d,
                                     unsigned long long a, unsigned long long b) {
    asm("fma.rn.f32x2 %0, %1, %2, %0;" : "+l"(d) : "l"(a), "l"(b));
}

// ---------------- Generic C = A(MxK) * B(NxK)^T + bias(N) ----------------
// BM=128, BN=64, BK=16, TM=8, TN=4, 256 threads.
// Accumulators packed in f32x2 pairs along M (2x FMA throughput vs FFMA).
template<int BM, int BN, int BK, int TM, int TN>
__global__ void __launch_bounds__(256)
gemm_abt_bias(const float* __restrict__ A, const float* __restrict__ Bm,
              const float* __restrict__ bias, float* __restrict__ C,
              int M, int N, int K)
{
    __shared__ __align__(16) float sA[BK][BM + 4];   // [k][m], stride 132 (16B-aligned rows)
    __shared__ __align__(16) float sB[BK][BN + 4];   // [k][n], stride 68

    const int tid = threadIdx.x;
    const int tn  = tid & 15;    // col group (TN cols each)
    const int tm  = tid >> 4;    // row group (TM rows each)
    const int m0  = blockIdx.x * BM;
    const int n0  = blockIdx.y * BN;

    const int lk = tid & 15;     // k index for cooperative loads
    const int lr = tid >> 4;     // row-group for cooperative loads

    unsigned long long acc[TM / 2][TN];
#pragma unroll
    for (int i = 0; i < TM / 2; i++)
#pragma unroll
        for (int j = 0; j < TN; j++) acc[i][j] = 0ULL;

    const int ktiles = (K + BK - 1) / BK;
    for (int kt = 0; kt < ktiles; kt++) {
        const int k0 = kt * BK;
        // A tile: rows m0+lr+16r, col k0+lk  (zero-fill OOB)
#pragma unroll
        for (int r = 0; r < BM / 16; r++) {
            int m = m0 + lr + 16 * r;
            int k = k0 + lk;
            float v = 0.f;
            if (k < K && m < M) v = A[(size_t)m * K + k];
            sA[lk][lr + 16 * r] = v;
        }
        // B tile: rows n0+lr+16r, col k0+lk  (zero-fill OOB)
#pragma unroll
        for (int r = 0; r < BN / 16; r++) {
            int n = n0 + lr + 16 * r;
            int k = k0 + lk;
            float v = 0.f;
            if (k < K && n < N) v = Bm[(size_t)n * K + k];
            sB[lk][lr + 16 * r] = v;
        }
        __syncthreads();

#pragma unroll
        for (int kk = 0; kk < BK; kk++) {
            float4 a0 = *(const float4*)&sA[kk][tm * TM];
            float4 a1 = *(const float4*)&sA[kk][tm * TM + 4];
            float4 b  = *(const float4*)&sB[kk][tn * TN];
            unsigned long long ap[4] = { pk2(a0.x, a0.y), pk2(a0.z, a0.w),
                                         pk2(a1.x, a1.y), pk2(a1.z, a1.w) };
            unsigned long long bd[4] = { pk2(b.x, b.x), pk2(b.y, b.y),
                                         pk2(b.z, b.z), pk2(b.w, b.w) };
#pragma unroll
            for (int i = 0; i < 4; i++)
#pragma unroll
                for (int j = 0; j < 4; j++)
                    fma2(acc[i][j], ap[i], bd[j]);
        }
        __syncthreads();
    }

    // Epilogue: unpack pairs (rows 2i, 2i+1 of this thread tile) + bias
#pragma unroll
    for (int i = 0; i < TM / 2; i++) {
        int mA = m0 + tm * TM + 2 * i;
#pragma unroll
        for (int j = 0; j < TN; j++) {
            int n = n0 + tn * TN + j;
            if (n < N) {
                float lo, hi;
                upk2(acc[i][j], lo, hi);
                float bb = bias[n];
                if (mA < M)     C[(size_t)mA * N + n]       = lo + bb;
                if (mA + 1 < M) C[(size_t)(mA + 1) * N + n] = hi + bb;
            }
        }
    }
}

// ---------------- LSTM recurrence over the BATCH axis ----------------
// T=512 independent lanes; each CTA owns 2 lanes for all 64 steps.
// W_hh lives in shared (transposed to [k][g] for conflict-free broadcast reads).
__global__ void __launch_bounds__(256)
lstm_rec_kernel(const float* __restrict__ xg, const float* __restrict__ W_hh,
                const float* __restrict__ b_hh, float* __restrict__ hs)
{
    __shared__ float sW[H_ * G_];     // sW[k*200 + g] = W_hh[g][k]
    __shared__ float sb[G_];
    __shared__ float h_sh[2][H_];
    __shared__ float gbuf[2][G_];

    const int tid = threadIdx.x;

    for (int idx = tid; idx < H_ * G_; idx += 256) {
        int g = idx / H_, k = idx % H_;
        sW[k * G_ + g] = W_hh[idx];           // W_hh is (200,50) row-major
    }
    if (tid < G_)      sb[tid] = b_hh[tid];
    if (tid < 2 * H_)  h_sh[tid / H_][tid % H_] = 0.f;
    float c = 0.f;                            // cell state (threads < 100)
    __syncthreads();

    const int lane0 = blockIdx.x * 2;         // lanes [lane0, lane0+1]

    for (int b = 0; b < B_; b++) {
        if (tid < G_) {
            const float* xr = xg + (size_t)(b * T_ + lane0) * G_;
            float a0a = xr[tid]      + sb[tid];   // xg already includes b_ih
            float a1a = xr[G_ + tid] + sb[tid];
            float a0b = 0.f, a1b = 0.f;
#pragma unroll
            for (int k = 0; k < H_; k += 2) {     // 2 dep chains per lane
                float w0 = sW[k * G_ + tid];
                float w1 = sW[(k + 1) * G_ + tid];
                a0a += h_sh[0][k] * w0;     a1a += h_sh[1][k] * w0;
                a0b += h_sh[0][k + 1] * w1; a1b += h_sh[1][k + 1] * w1;
            }
            gbuf[0][tid] = a0a + a0b;
            gbuf[1][tid] = a1a + a1b;
        }
        __syncthreads();

        if (tid < 2 * H_) {
            int l = tid / H_, hh = tid % H_;
            float ig = gbuf[l][hh];
            float fg = gbuf[l][H_ + hh];
            float gg = gbuf[l][2 * H_ + hh];
            float og = gbuf[l][3 * H_ + hh];
            float si = 1.f / (1.f + expf(-ig));
            float sf = 1.f / (1.f + expf(-fg));
            float so = 1.f / (1.f + expf(-og));
            c = sf * c + si * tanhf(gg);
            float h2 = so * tanhf(c);
            h_sh[l][hh] = h2;
            hs[(size_t)(b * T_ + lane0 + l) * H_ + hh] = h2;
        }
        __syncthreads();   // h_sh ready for next step's gate reads
    }
}

// ---------------- launch ----------------
extern "C" void kernel_launch(void* const* d_in, const int* in_sizes, int n_in,
                              void* d_out, int out_size)
{
    const float* x     = (const float*)d_in[0];   // (64,512,513)
    const float* W_ih  = (const float*)d_in[1];   // (200,513)
    const float* W_hh  = (const float*)d_in[2];   // (200,50)
    const float* b_ih  = (const float*)d_in[3];   // (200,)
    const float* b_hh  = (const float*)d_in[4];   // (200,)
    const float* W_out = (const float*)d_in[5];   // (513,50)
    const float* b_out = (const float*)d_in[6];   // (513,)
    float* out = (float*)d_out;                   // (64,512,513)

    float *xg, *hs;
    cudaGetSymbolAddress((void**)&xg, g_xg);
    cudaGetSymbolAddress((void**)&hs, g_hs);

    dim3 blk(256);

    // 1) xg = x @ W_ih^T + b_ih   (M=32768, N=200, K=513)
    gemm_abt_bias<128, 64, 16, 8, 4>
        <<<dim3(M_ / 128, (G_ + 63) / 64), blk>>>(x, W_ih, b_ih, xg, M_, G_, F_);

    // 2) batch-axis LSTM recurrence -> hs (32768, 50)
    lstm_rec_kernel<<<T_ / 2, blk>>>(xg, W_hh, b_hh, hs);

    // 3) out = hs @ W_out^T + b_out   (M=32768, N=513, K=50)
    gemm_abt_bias<128, 64, 16, 8, 4>
        <<<dim3(M_ / 128, (F_ + 63) / 64), blk>>>(hs, W_out, b_out, out, M_, F_, H_);
}